// round 6
// baseline (speedup 1.0000x reference)
#include <cuda_runtime.h>
#include <math.h>
#include <stdint.h>

// ---------------- problem constants ----------------
#define DIMC   768
#define D3     2304
#define NH     12
#define HD     64
#define SEQ_S  1025
#define MLPH   3072
#define NTOK_T 8192      // 2*4096 temporal tokens
#define NTOK_S 8200      // 8*1025 spatial tokens
#define NTOK_O 8194      // 2*4097 output tokens
#define PAD_ROWS 8320    // 65*128 (GEMM M padding)
#define BIAS_HW (1025*1025)

// ---------------- scratch (device globals; no allocs allowed) ----------------
__device__ __align__(16) float g_ln  [PAD_ROWS * DIMC];
__device__ __align__(16) float g_qkv [PAD_ROWS * D3];
__device__ __align__(16) float g_att [PAD_ROWS * DIMC];
__device__ __align__(16) float g_res [PAD_ROWS * DIMC];
__device__ __align__(16) float g_xt  [8192 * DIMC];
__device__ __align__(16) float g_bias[NH * BIAS_HW];
__device__ __align__(16) float g_h   [PAD_ROWS * MLPH];

// ---------------- block reduction ----------------
__device__ __forceinline__ float block_reduce_sum(float v) {
    __shared__ float red[8];
    int lane = threadIdx.x & 31, wid = threadIdx.x >> 5;
    #pragma unroll
    for (int o = 16; o; o >>= 1) v += __shfl_xor_sync(0xffffffffu, v, o);
    if (lane == 0) red[wid] = v;
    __syncthreads();
    if (wid == 0) {
        float r = (lane < 8) ? red[lane] : 0.f;
        #pragma unroll
        for (int o = 4; o; o >>= 1) r += __shfl_xor_sync(0xffffffffu, r, o);
        if (lane == 0) red[0] = r;
    }
    __syncthreads();
    float s = red[0];
    __syncthreads();
    return s;
}

// LayerNorm of one 768-row; blockDim = 256
__device__ __forceinline__ void ln_row(const float* __restrict__ src,
                                       float* __restrict__ dst,
                                       const float* __restrict__ g,
                                       const float* __restrict__ b) {
    int t = threadIdx.x;
    float v0 = src[t], v1 = src[t + 256], v2 = src[t + 512];
    float s = block_reduce_sum(v0 + v1 + v2);
    float mean = s * (1.0f / 768.0f);
    float d0 = v0 - mean, d1 = v1 - mean, d2 = v2 - mean;
    float vs = block_reduce_sum(d0 * d0 + d1 * d1 + d2 * d2);
    float rstd = rsqrtf(vs * (1.0f / 768.0f) + 1e-5f);
    dst[t]       = d0 * rstd * g[t]       + b[t];
    dst[t + 256] = d1 * rstd * g[t + 256] + b[t + 256];
    dst[t + 512] = d2 * rstd * g[t + 512] + b[t + 512];
}

// x[:,1:,:] rows -> LN -> g_ln  (row r: b=r>>12, pos=r&4095)
__global__ void ln_temporal(const float* __restrict__ x,
                            const float* __restrict__ g, const float* __restrict__ b) {
    int row = blockIdx.x;
    int bb = row >> 12, pos = row & 4095;
    ln_row(x + (size_t)(bb * 4097 + 1 + pos) * DIMC, g_ln + (size_t)row * DIMC, g, b);
}

// gather xs (cls | permuted xt) -> LN -> g_ln ; row = bt*1025 + n
__global__ void ln_spatial(const float* __restrict__ x,
                           const float* __restrict__ g, const float* __restrict__ b) {
    int row = blockIdx.x;
    int bt = row / 1025, n = row % 1025;
    int bb = bt >> 2, t = bt & 3;
    const float* src = (n == 0)
        ? x + (size_t)bb * 4097 * DIMC
        : g_xt + (size_t)(bb * 4096 + (n - 1) * 4 + t) * DIMC;
    ln_row(src, g_ln + (size_t)row * DIMC, g, b);
}

// LN of xout (contiguous d_out rows) -> g_ln
__global__ void ln_plain(const float* __restrict__ xo,
                         const float* __restrict__ g, const float* __restrict__ b) {
    int row = blockIdx.x;
    ln_row(xo + (size_t)row * DIMC, g_ln + (size_t)row * DIMC, g, b);
}

// ---------------- SGEMM: C[M,N] = A[M,K] @ W[N,K]^T (+bias) (+epilogue) ----------------
// BM=BN=128, BK=8, 256 threads, 8x8 microtile.
enum { E_NONE = 0, E_GELU = 1, E_RES = 2 };

template <int EPI>
__global__ void __launch_bounds__(256, 2)
sgemm_nt(const float* __restrict__ A, const float* __restrict__ W,
         const float* __restrict__ bias, float* __restrict__ C,
         int M, int N, int K) {
    __shared__ __align__(16) float As[8][128];
    __shared__ __align__(16) float Ws[8][128];
    const int tid = threadIdx.x;
    const int bm = blockIdx.y * 128;
    const int bn = blockIdx.x * 128;
    const int lrow = tid >> 1;
    const int lcol = (tid & 1) * 4;
    const int tr = (tid >> 4) * 8;
    const int tc = (tid & 15) * 8;

    float acc[8][8] = {};
    const float* Aptr = A + (size_t)(bm + lrow) * K + lcol;  // rows padded; safe
    const float* Wptr = W + (size_t)(bn + lrow) * K + lcol;

    for (int k0 = 0; k0 < K; k0 += 8) {
        float4 av = *(const float4*)(Aptr + k0);
        float4 wv = *(const float4*)(Wptr + k0);
        As[lcol + 0][lrow] = av.x; As[lcol + 1][lrow] = av.y;
        As[lcol + 2][lrow] = av.z; As[lcol + 3][lrow] = av.w;
        Ws[lcol + 0][lrow] = wv.x; Ws[lcol + 1][lrow] = wv.y;
        Ws[lcol + 2][lrow] = wv.z; Ws[lcol + 3][lrow] = wv.w;
        __syncthreads();
        #pragma unroll
        for (int kk = 0; kk < 8; kk++) {
            float4 a0 = *(const float4*)&As[kk][tr];
            float4 a1 = *(const float4*)&As[kk][tr + 4];
            float4 b0 = *(const float4*)&Ws[kk][tc];
            float4 b1 = *(const float4*)&Ws[kk][tc + 4];
            float a[8] = {a0.x, a0.y, a0.z, a0.w, a1.x, a1.y, a1.z, a1.w};
            float w[8] = {b0.x, b0.y, b0.z, b0.w, b1.x, b1.y, b1.z, b1.w};
            #pragma unroll
            for (int i = 0; i < 8; i++)
                #pragma unroll
                for (int j = 0; j < 8; j++)
                    acc[i][j] += a[i] * w[j];
        }
        __syncthreads();
    }

    #pragma unroll
    for (int i = 0; i < 8; i++) {
        int row = bm + tr + i;
        if (row < M) {
            float* crow = C + (size_t)row * N + bn + tc;
            #pragma unroll
            for (int j = 0; j < 8; j++) {
                float v = acc[i][j];
                if (bias) v += bias[bn + tc + j];
                if (EPI == E_GELU) v = 0.5f * v * (1.0f + erff(v * 0.70710678118654752f));
                else if (EPI == E_RES) v += crow[j];
                crow[j] = v;
            }
        }
    }
}

// ---------------- temporal attention: seq=4, one warp per (seq,head) ----------------
__global__ void temporal_attn() {
    int w = (blockIdx.x * blockDim.x + threadIdx.x) >> 5;
    int lane = threadIdx.x & 31;
    if (w >= 2048 * NH) return;
    int sq = w / NH, h = w % NH;
    int col = h * HD + lane;

    float q[4][2], k[4][2], v[4][2];
    #pragma unroll
    for (int t = 0; t < 4; t++) {
        const float* base = g_qkv + (size_t)(sq * 4 + t) * D3;
        q[t][0] = base[col];            q[t][1] = base[col + 32];
        k[t][0] = base[768 + col];      k[t][1] = base[768 + col + 32];
        v[t][0] = base[1536 + col];     v[t][1] = base[1536 + col + 32];
    }
    float sc[4][4];
    #pragma unroll
    for (int t = 0; t < 4; t++)
        #pragma unroll
        for (int u = 0; u < 4; u++) {
            float p = q[t][0] * k[u][0] + q[t][1] * k[u][1];
            #pragma unroll
            for (int o = 16; o; o >>= 1) p += __shfl_xor_sync(0xffffffffu, p, o);
            sc[t][u] = p * 0.125f;
        }
    #pragma unroll
    for (int t = 0; t < 4; t++) {
        float m = fmaxf(fmaxf(sc[t][0], sc[t][1]), fmaxf(sc[t][2], sc[t][3]));
        float e0 = __expf(sc[t][0] - m), e1 = __expf(sc[t][1] - m);
        float e2 = __expf(sc[t][2] - m), e3 = __expf(sc[t][3] - m);
        float inv = 1.0f / (e0 + e1 + e2 + e3);
        float o0 = (e0 * v[0][0] + e1 * v[1][0] + e2 * v[2][0] + e3 * v[3][0]) * inv;
        float o1 = (e0 * v[0][1] + e1 * v[1][1] + e2 * v[2][1] + e3 * v[3][1]) * inv;
        float* dst = g_att + (size_t)(sq * 4 + t) * DIMC + col;
        dst[0] = o0; dst[32] = o1;
    }
}

// ---------------- geometry bias: g_bias[h, i, j] ----------------
__global__ void bias_kernel(const float* __restrict__ wg_w, const float* __restrict__ wg_b) {
    int idx = blockIdx.x * blockDim.x + threadIdx.x;
    if (idx >= BIAS_HW) return;
    int i = idx / 1025, j = idx % 1025;
    if (i == 0 || j == 0) {
        #pragma unroll
        for (int h = 0; h < NH; h++) g_bias[(size_t)h * BIAS_HW + idx] = 0.f;
        return;
    }
    int p = i - 1, q = j - 1;
    const float inv32 = 1.0f / 32.0f, half32 = 0.5f / 32.0f;
    float cxp = (float)(p >> 5) * inv32 + half32;
    float cyp = (float)(p & 31) * inv32 + half32;
    float cxq = (float)(q >> 5) * inv32 + half32;
    float cyq = (float)(q & 31) * inv32 + half32;
    const float invw = 1.0f / (1.0f + inv32);
    float dx = logf(fmaxf(fabsf((cxp - cxq) * invw), 0.001f));
    float dy = logf(fmaxf(fabsf((cyp - cyq) * invw), 0.001f));

    const float dm[8] = {1.0f, 0.42169650342f, 0.17782794100f, 0.074989420933f,
                         0.031622776602f, 0.013335214322f, 0.0056234132519f, 0.0023713737057f};
    float emb[64];
    float hdx = 100.0f * dx, hdy = 100.0f * dy;
    #pragma unroll
    for (int d = 0; d < 8; d++) {
        float sx, cx, sy, cy;
        sincosf(hdx * dm[d], &sx, &cx);
        sincosf(hdy * dm[d], &sy, &cy);
        emb[d] = sx;       emb[8 + d] = sy;
        emb[16 + d] = 0.f; emb[24 + d] = 0.f;
        emb[32 + d] = cx;  emb[40 + d] = cy;
        emb[48 + d] = 1.f; emb[56 + d] = 1.f;
    }
    for (int h = 0; h < NH; h++) {
        float acc = wg_b[h];
        const float* wr = wg_w + h * 64;
        #pragma unroll
        for (int d = 0; d < 64; d++) acc += emb[d] * wr[d];
        float w = fmaxf(acc, 0.f);
        g_bias[(size_t)h * BIAS_HW + idx] = logf(fmaxf(w, 1e-6f));
    }
}

// ---------------- fused spatial attention (flash-style), 64q x 32k tiles ----------------
__global__ void __launch_bounds__(256) spatial_attn() {
    __shared__ __align__(16) float Qs[64][64];  // [d][q]
    __shared__ __align__(16) float Ks[64][32];  // [d][k]
    __shared__ __align__(16) float Vs[32][64];  // [k][d]
    __shared__ __align__(16) float Ps[32][64];  // [k][q]

    const int tid = threadIdx.x;
    const int ty = tid >> 4, tx = tid & 15;
    const int qtile = blockIdx.x;      // 0..16
    const int h = blockIdx.y;          // 0..11
    const int bt = blockIdx.z;         // 0..7
    const int q0 = qtile * 64;

    // load Q tile (transposed into [d][q])
    {
        int q = tid >> 2;
        int dbase = (tid & 3) * 16;
        int qc = min(q0 + q, 1024);
        const float* src = g_qkv + (size_t)(bt * 1025 + qc) * D3 + h * HD + dbase;
        #pragma unroll
        for (int z = 0; z < 16; z++) Qs[dbase + z][q] = src[z];
    }

    float mi[4] = {-1e30f, -1e30f, -1e30f, -1e30f};
    float li[4] = {0.f, 0.f, 0.f, 0.f};
    float acc[4][4] = {};
    const float* brow_base = g_bias + (size_t)h * BIAS_HW;

    for (int kt = 0; kt < 33; kt++) {
        const int k0 = kt * 32;
        __syncthreads();   // protect Ks/Vs/Ps from previous iteration's readers
        {
            int k = tid >> 3;
            int dbase = (tid & 7) * 8;
            int kg = k0 + k;
            if (kg < 1025) {
                const float* src = g_qkv + (size_t)(bt * 1025 + kg) * D3 + 768 + h * HD + dbase;
                #pragma unroll
                for (int z = 0; z < 8; z++) {
                    Ks[dbase + z][k] = src[z];
                    Vs[k][dbase + z] = src[768 + z];
                }
            } else {
                #pragma unroll
                for (int z = 0; z < 8; z++) { Ks[dbase + z][k] = 0.f; Vs[k][dbase + z] = 0.f; }
            }
        }
        __syncthreads();

        // S = Q K^T  (thread: 4 queries x 2 keys)
        float sv[4][2] = {};
        #pragma unroll 16
        for (int d = 0; d < 64; d++) {
            float4 qa = *(const float4*)&Qs[d][ty * 4];
            float2 kb = *(const float2*)&Ks[d][tx * 2];
            sv[0][0] += qa.x * kb.x; sv[0][1] += qa.x * kb.y;
            sv[1][0] += qa.y * kb.x; sv[1][1] += qa.y * kb.y;
            sv[2][0] += qa.z * kb.x; sv[2][1] += qa.z * kb.y;
            sv[3][0] += qa.w * kb.x; sv[3][1] += qa.w * kb.y;
        }

        float pr[4][2];
        #pragma unroll
        for (int i = 0; i < 4; i++) {
            int qc = min(q0 + ty * 4 + i, 1024);
            const float* brow = brow_base + (size_t)qc * 1025;
            float lg[2];
            #pragma unroll
            for (int j = 0; j < 2; j++) {
                int kg = k0 + tx * 2 + j;
                float bz = brow[min(kg, 1024)];
                lg[j] = (kg < 1025) ? sv[i][j] * 0.125f + bz : -1e30f;
            }
            float rm = fmaxf(lg[0], lg[1]);
            #pragma unroll
            for (int o = 1; o < 16; o <<= 1) rm = fmaxf(rm, __shfl_xor_sync(0xffffffffu, rm, o));
            float mnew = fmaxf(mi[i], rm);
            float p0 = __expf(lg[0] - mnew), p1 = __expf(lg[1] - mnew);
            float rs = p0 + p1;
            #pragma unroll
            for (int o = 1; o < 16; o <<= 1) rs += __shfl_xor_sync(0xffffffffu, rs, o);
            float corr = __expf(mi[i] - mnew);
            li[i] = li[i] * corr + rs;
            mi[i] = mnew;
            acc[i][0] *= corr; acc[i][1] *= corr; acc[i][2] *= corr; acc[i][3] *= corr;
            pr[i][0] = p0; pr[i][1] = p1;
        }
        #pragma unroll
        for (int j = 0; j < 2; j++) {
            float4 pv = {pr[0][j], pr[1][j], pr[2][j], pr[3][j]};
            *(float4*)&Ps[tx * 2 + j][ty * 4] = pv;
        }
        __syncthreads();

        // O += P @ V
        #pragma unroll 8
        for (int kk = 0; kk < 32; kk++) {
            float4 pv = *(const float4*)&Ps[kk][ty * 4];
            float4 vv = *(const float4*)&Vs[kk][tx * 4];
            acc[0][0] += pv.x * vv.x; acc[0][1] += pv.x * vv.y; acc[0][2] += pv.x * vv.z; acc[0][3] += pv.x * vv.w;
            acc[1][0] += pv.y * vv.x; acc[1][1] += pv.y * vv.y; acc[1][2] += pv.y * vv.z; acc[1][3] += pv.y * vv.w;
            acc[2][0] += pv.z * vv.x; acc[2][1] += pv.z * vv.y; acc[2][2] += pv.z * vv.z; acc[2][3] += pv.z * vv.w;
            acc[3][0] += pv.w * vv.x; acc[3][1] += pv.w * vv.y; acc[3][2] += pv.w * vv.z; acc[3][3] += pv.w * vv.w;
        }
    }

    #pragma unroll
    for (int i = 0; i < 4; i++) {
        int qg = q0 + ty * 4 + i;
        if (qg < 1025) {
            float inv = 1.0f / li[i];
            float4 o = {acc[i][0] * inv, acc[i][1] * inv, acc[i][2] * inv, acc[i][3] * inv};
            *(float4*)(g_att + (size_t)(bt * 1025 + qg) * DIMC + h * HD + tx * 4) = o;
        }
    }
}

// ---------------- elementwise: g_xt = x[:,1:,:] + tfc_out(g_att) ----------------
__global__ void add_xt(const float* __restrict__ x) {
    int i4 = blockIdx.x * blockDim.x + threadIdx.x;
    const int total = 8192 * 192;
    if (i4 >= total) return;
    int row = i4 / 192, c4 = i4 - row * 192;
    int bb = row >> 12, pos = row & 4095;
    float4 a = ((const float4*)g_att)[i4];
    float4 xv = ((const float4*)x)[(size_t)(bb * 4097 + 1 + pos) * 192 + c4];
    float4 r = {a.x + xv.x, a.y + xv.y, a.z + xv.z, a.w + xv.w};
    ((float4*)g_xt)[i4] = r;
}

// ---------------- assemble xout into d_out ----------------
__global__ void assemble(const float* __restrict__ x, float* __restrict__ out) {
    int i4 = blockIdx.x * blockDim.x + threadIdx.x;
    const int total = 2 * 4097 * 192;
    if (i4 >= total) return;
    int rem = i4 / 192, c4 = i4 - rem * 192;
    int bb = rem / 4097, n = rem - bb * 4097;
    const float4* res4 = (const float4*)g_res;
    float4 r;
    if (n == 0) {
        float4 a = ((const float4*)x)[i4];
        float4 s = {0.f, 0.f, 0.f, 0.f};
        #pragma unroll
        for (int t = 0; t < 4; t++) {
            float4 v = res4[(size_t)((bb * 4 + t) * 1025) * 192 + c4];
            s.x += v.x; s.y += v.y; s.z += v.z; s.w += v.w;
        }
        r = {a.x + 0.25f * s.x, a.y + 0.25f * s.y, a.z + 0.25f * s.z, a.w + 0.25f * s.w};
    } else {
        int st = n - 1, ss = st >> 2, t = st & 3;
        float4 a = ((const float4*)g_xt)[(size_t)(bb * 4096 + st) * 192 + c4];
        float4 v = res4[(size_t)((bb * 4 + t) * 1025 + 1 + ss) * 192 + c4];
        r = {a.x + v.x, a.y + v.y, a.z + v.z, a.w + v.w};
    }
    ((float4*)out)[i4] = r;
}

// ---------------- host launch sequence ----------------
extern "C" void kernel_launch(void* const* d_in, const int* in_sizes, int n_in,
                              void* d_out, int out_size) {
    const float* x        = (const float*)d_in[0];
    const float* norm1_g  = (const float*)d_in[1];
    const float* norm1_b  = (const float*)d_in[2];
    const float* qkv_w    = (const float*)d_in[3];
    const float* proj_w   = (const float*)d_in[4];
    const float* proj_b   = (const float*)d_in[5];
    const float* wg_w     = (const float*)d_in[6];
    const float* wg_b     = (const float*)d_in[7];
    const float* tnorm1_g = (const float*)d_in[8];
    const float* tnorm1_b = (const float*)d_in[9];
    const float* tqkv_w   = (const float*)d_in[10];
    const float* tproj_w  = (const float*)d_in[11];
    const float* tproj_b  = (const float*)d_in[12];
    const float* tfc_w    = (const float*)d_in[13];
    const float* tfc_b    = (const float*)d_in[14];
    const float* norm2_g  = (const float*)d_in[15];
    const float* norm2_b  = (const float*)d_in[16];
    const float* fc1_w    = (const float*)d_in[17];
    const float* fc1_b    = (const float*)d_in[18];
    const float* fc2_w    = (const float*)d_in[19];
    const float* fc2_b    = (const float*)d_in[20];
    float* out = (float*)d_out;

    float *ln, *qkv, *att, *res, *hbuf;
    cudaGetSymbolAddress((void**)&ln,   g_ln);
    cudaGetSymbolAddress((void**)&qkv,  g_qkv);
    cudaGetSymbolAddress((void**)&att,  g_att);
    cudaGetSymbolAddress((void**)&res,  g_res);
    cudaGetSymbolAddress((void**)&hbuf, g_h);

    // geometry bias (independent of main chain)
    bias_kernel<<<(BIAS_HW + 255) / 256, 256>>>(wg_w, wg_b);

    // --- temporal branch ---
    ln_temporal<<<NTOK_T, 256>>>(x, tnorm1_g, tnorm1_b);
    sgemm_nt<E_NONE><<<dim3(D3 / 128, NTOK_T / 128), 256>>>(ln, tqkv_w, nullptr, qkv, NTOK_T, D3, DIMC);
    temporal_attn<<<3072, 256>>>();
    sgemm_nt<E_NONE><<<dim3(DIMC / 128, NTOK_T / 128), 256>>>(att, tproj_w, tproj_b, res, NTOK_T, DIMC, DIMC);
    sgemm_nt<E_NONE><<<dim3(DIMC / 128, NTOK_T / 128), 256>>>(res, tfc_w, tfc_b, att, NTOK_T, DIMC, DIMC);
    add_xt<<<(8192 * 192 + 255) / 256, 256>>>(x);

    // --- spatial branch ---
    ln_spatial<<<NTOK_S, 256>>>(x, norm1_g, norm1_b);
    sgemm_nt<E_NONE><<<dim3(D3 / 128, (NTOK_S + 127) / 128), 256>>>(ln, qkv_w, nullptr, qkv, NTOK_S, D3, DIMC);
    spatial_attn<<<dim3(17, NH, 8), 256>>>();
    sgemm_nt<E_NONE><<<dim3(DIMC / 128, (NTOK_S + 127) / 128), 256>>>(att, proj_w, proj_b, res, NTOK_S, DIMC, DIMC);
    assemble<<<(2 * 4097 * 192 + 255) / 256, 256>>>(x, out);

    // --- MLP ---
    ln_plain<<<NTOK_O, 256>>>(out, norm2_g, norm2_b);
    sgemm_nt<E_GELU><<<dim3(MLPH / 128, (NTOK_O + 127) / 128), 256>>>(ln, fc1_w, fc1_b, hbuf, NTOK_O, MLPH, DIMC);
    sgemm_nt<E_RES><<<dim3(DIMC / 128, (NTOK_O + 127) / 128), 256>>>(hbuf, fc2_w, fc2_b, out, NTOK_O, DIMC, MLPH);
}

// round 7
// speedup vs baseline: 1.0137x; 1.0137x over previous
#include <cuda_runtime.h>
#include <math.h>
#include <stdint.h>

// ---------------- problem constants ----------------
#define DIMC   768
#define D3     2304
#define NH     12
#define HD     64
#define SEQ_S  1025
#define MLPH   3072
#define NTOK_T 8192      // 2*4096 temporal tokens
#define NTOK_S 8200      // 8*1025 spatial tokens
#define NTOK_O 8194      // 2*4097 output tokens
#define PAD_ROWS 8320    // 65*128 (GEMM M padding)
#define BIAS_HW (1025*1025)

// ---------------- scratch (device globals; no allocs allowed) ----------------
__device__ __align__(16) float g_ln  [PAD_ROWS * DIMC];
__device__ __align__(16) float g_qkv [PAD_ROWS * D3];
__device__ __align__(16) float g_att [PAD_ROWS * DIMC];
__device__ __align__(16) float g_res [PAD_ROWS * DIMC];
__device__ __align__(16) float g_xt  [8192 * DIMC];
__device__ __align__(16) float g_bias[NH * BIAS_HW];
__device__ __align__(16) float g_tab [NH * 32 * 32];
__device__ __align__(16) float g_h   [PAD_ROWS * MLPH];

// ---------------- packed f32x2 helpers (sm_100+ dual-issue fp32 FMA) ----------------
__device__ __forceinline__ unsigned long long dup2(float v) {
    unsigned long long r;
    unsigned u = __float_as_uint(v);
    asm("mov.b64 %0, {%1, %1};" : "=l"(r) : "r"(u));
    return r;
}
#define FMA2(acc, a, b) \
    asm("fma.rn.f32x2 %0, %1, %2, %3;" : "=l"(acc) : "l"(a), "l"(b), "l"(acc))
#define MUL2(dst, a, b) \
    asm("mul.rn.f32x2 %0, %1, %2;" : "=l"(dst) : "l"(a), "l"(b))
__device__ __forceinline__ void unpack2(unsigned long long p, float& lo, float& hi) {
    unsigned ulo, uhi;
    asm("mov.b64 {%0, %1}, %2;" : "=r"(ulo), "=r"(uhi) : "l"(p));
    lo = __uint_as_float(ulo); hi = __uint_as_float(uhi);
}

// ---------------- block reduction ----------------
__device__ __forceinline__ float block_reduce_sum(float v) {
    __shared__ float red[8];
    int lane = threadIdx.x & 31, wid = threadIdx.x >> 5;
    #pragma unroll
    for (int o = 16; o; o >>= 1) v += __shfl_xor_sync(0xffffffffu, v, o);
    if (lane == 0) red[wid] = v;
    __syncthreads();
    if (wid == 0) {
        float r = (lane < 8) ? red[lane] : 0.f;
        #pragma unroll
        for (int o = 4; o; o >>= 1) r += __shfl_xor_sync(0xffffffffu, r, o);
        if (lane == 0) red[0] = r;
    }
    __syncthreads();
    float s = red[0];
    __syncthreads();
    return s;
}

// LayerNorm of one 768-row; blockDim = 256
__device__ __forceinline__ void ln_row(const float* __restrict__ src,
                                       float* __restrict__ dst,
                                       const float* __restrict__ g,
                                       const float* __restrict__ b) {
    int t = threadIdx.x;
    float v0 = src[t], v1 = src[t + 256], v2 = src[t + 512];
    float s = block_reduce_sum(v0 + v1 + v2);
    float mean = s * (1.0f / 768.0f);
    float d0 = v0 - mean, d1 = v1 - mean, d2 = v2 - mean;
    float vs = block_reduce_sum(d0 * d0 + d1 * d1 + d2 * d2);
    float rstd = rsqrtf(vs * (1.0f / 768.0f) + 1e-5f);
    dst[t]       = d0 * rstd * g[t]       + b[t];
    dst[t + 256] = d1 * rstd * g[t + 256] + b[t + 256];
    dst[t + 512] = d2 * rstd * g[t + 512] + b[t + 512];
}

__global__ void ln_temporal(const float* __restrict__ x,
                            const float* __restrict__ g, const float* __restrict__ b) {
    int row = blockIdx.x;
    int bb = row >> 12, pos = row & 4095;
    ln_row(x + (size_t)(bb * 4097 + 1 + pos) * DIMC, g_ln + (size_t)row * DIMC, g, b);
}

__global__ void ln_spatial(const float* __restrict__ x,
                           const float* __restrict__ g, const float* __restrict__ b) {
    int row = blockIdx.x;
    int bt = row / 1025, n = row % 1025;
    int bb = bt >> 2, t = bt & 3;
    const float* src = (n == 0)
        ? x + (size_t)bb * 4097 * DIMC
        : g_xt + (size_t)(bb * 4096 + (n - 1) * 4 + t) * DIMC;
    ln_row(src, g_ln + (size_t)row * DIMC, g, b);
}

__global__ void ln_plain(const float* __restrict__ xo,
                         const float* __restrict__ g, const float* __restrict__ b) {
    int row = blockIdx.x;
    ln_row(xo + (size_t)row * DIMC, g_ln + (size_t)row * DIMC, g, b);
}

// ---------------- SGEMM: C[M,N] = A[M,K] @ W[N,K]^T (+bias) (+epilogue) ----------------
// BM=BN=128, BK=8, 256 threads, 8x8 microtile, packed f32x2 FMAs.
enum { E_NONE = 0, E_GELU = 1, E_RES = 2 };

template <int EPI>
__global__ void __launch_bounds__(256, 2)
sgemm_nt(const float* __restrict__ A, const float* __restrict__ W,
         const float* __restrict__ bias, float* __restrict__ C,
         int M, int N, int K) {
    __shared__ __align__(16) float As[8][128];
    __shared__ __align__(16) float Ws[8][128];
    const int tid = threadIdx.x;
    const int bm = blockIdx.y * 128;
    const int bn = blockIdx.x * 128;
    const int lrow = tid >> 1;
    const int lcol = (tid & 1) * 4;
    const int tr = (tid >> 4) * 8;
    const int tc = (tid & 15) * 8;

    unsigned long long acc[8][4] = {};   // acc[i][j2] packs columns {2*j2, 2*j2+1}
    const float* Aptr = A + (size_t)(bm + lrow) * K + lcol;  // rows padded; safe
    const float* Wptr = W + (size_t)(bn + lrow) * K + lcol;

    for (int k0 = 0; k0 < K; k0 += 8) {
        float4 av = *(const float4*)(Aptr + k0);
        float4 wv = *(const float4*)(Wptr + k0);
        As[lcol + 0][lrow] = av.x; As[lcol + 1][lrow] = av.y;
        As[lcol + 2][lrow] = av.z; As[lcol + 3][lrow] = av.w;
        Ws[lcol + 0][lrow] = wv.x; Ws[lcol + 1][lrow] = wv.y;
        Ws[lcol + 2][lrow] = wv.z; Ws[lcol + 3][lrow] = wv.w;
        __syncthreads();
        #pragma unroll
        for (int kk = 0; kk < 8; kk++) {
            float4 a0 = *(const float4*)&As[kk][tr];
            float4 a1 = *(const float4*)&As[kk][tr + 4];
            ulonglong2 w0 = *(const ulonglong2*)&Ws[kk][tc];
            ulonglong2 w1 = *(const ulonglong2*)&Ws[kk][tc + 4];
            unsigned long long bp[4] = {w0.x, w0.y, w1.x, w1.y};
            float am[8] = {a0.x, a0.y, a0.z, a0.w, a1.x, a1.y, a1.z, a1.w};
            #pragma unroll
            for (int i = 0; i < 8; i++) {
                unsigned long long ad = dup2(am[i]);
                #pragma unroll
                for (int j = 0; j < 4; j++) FMA2(acc[i][j], ad, bp[j]);
            }
        }
        __syncthreads();
    }

    #pragma unroll
    for (int i = 0; i < 8; i++) {
        int row = bm + tr + i;
        if (row < M) {
            float* crow = C + (size_t)row * N + bn + tc;
            #pragma unroll
            for (int j2 = 0; j2 < 4; j2++) {
                float v0, v1;
                unpack2(acc[i][j2], v0, v1);
                float vv[2] = {v0, v1};
                #pragma unroll
                for (int u = 0; u < 2; u++) {
                    int j = 2 * j2 + u;
                    float v = vv[u];
                    if (bias) v += bias[bn + tc + j];
                    if (EPI == E_GELU) v = 0.5f * v * (1.0f + erff(v * 0.70710678118654752f));
                    else if (EPI == E_RES) v += crow[j];
                    crow[j] = v;
                }
            }
        }
    }
}

// ---------------- temporal attention: seq=4, one warp per (seq,head) ----------------
__global__ void temporal_attn() {
    int w = (blockIdx.x * blockDim.x + threadIdx.x) >> 5;
    int lane = threadIdx.x & 31;
    if (w >= 2048 * NH) return;
    int sq = w / NH, h = w % NH;
    int col = h * HD + lane;

    float q[4][2], k[4][2], v[4][2];
    #pragma unroll
    for (int t = 0; t < 4; t++) {
        const float* base = g_qkv + (size_t)(sq * 4 + t) * D3;
        q[t][0] = base[col];            q[t][1] = base[col + 32];
        k[t][0] = base[768 + col];      k[t][1] = base[768 + col + 32];
        v[t][0] = base[1536 + col];     v[t][1] = base[1536 + col + 32];
    }
    float sc[4][4];
    #pragma unroll
    for (int t = 0; t < 4; t++)
        #pragma unroll
        for (int u = 0; u < 4; u++) {
            float p = q[t][0] * k[u][0] + q[t][1] * k[u][1];
            #pragma unroll
            for (int o = 16; o; o >>= 1) p += __shfl_xor_sync(0xffffffffu, p, o);
            sc[t][u] = p * 0.125f;
        }
    #pragma unroll
    for (int t = 0; t < 4; t++) {
        float m = fmaxf(fmaxf(sc[t][0], sc[t][1]), fmaxf(sc[t][2], sc[t][3]));
        float e0 = __expf(sc[t][0] - m), e1 = __expf(sc[t][1] - m);
        float e2 = __expf(sc[t][2] - m), e3 = __expf(sc[t][3] - m);
        float inv = 1.0f / (e0 + e1 + e2 + e3);
        float o0 = (e0 * v[0][0] + e1 * v[1][0] + e2 * v[2][0] + e3 * v[3][0]) * inv;
        float o1 = (e0 * v[0][1] + e1 * v[1][1] + e2 * v[2][1] + e3 * v[3][1]) * inv;
        float* dst = g_att + (size_t)(sq * 4 + t) * DIMC + col;
        dst[0] = o0; dst[32] = o1;
    }
}

// ---------------- geometry bias via factored table ----------------
// bias[h, i, j] (i,j >= 1) depends ONLY on (|Δpx|, |Δpy|) of the two patches:
// 12 heads x 32 x 32 distinct values. Compute table, then pure-store fill.
__global__ void bias_table(const float* __restrict__ wg_w, const float* __restrict__ wg_b) {
    int idx = blockIdx.x * blockDim.x + threadIdx.x;
    if (idx >= NH * 1024) return;
    int h = idx >> 10;
    int rc = idx & 1023;
    int r = rc >> 5, c = rc & 31;     // |Δpx|, |Δpy| in 0..31
    const float invw = 1.0f / (1.0f + 1.0f / 32.0f);
    float dx = logf(fmaxf(((float)r / 32.0f) * invw, 0.001f));
    float dy = logf(fmaxf(((float)c / 32.0f) * invw, 0.001f));

    const float dm[8] = {1.0f, 0.42169650342f, 0.17782794100f, 0.074989420933f,
                         0.031622776602f, 0.013335214322f, 0.0056234132519f, 0.0023713737057f};
    float emb[64];
    float hdx = 100.0f * dx, hdy = 100.0f * dy;
    #pragma unroll
    for (int d = 0; d < 8; d++) {
        float sx, cx, sy, cy;
        sincosf(hdx * dm[d], &sx, &cx);
        sincosf(hdy * dm[d], &sy, &cy);
        emb[d] = sx;       emb[8 + d] = sy;
        emb[16 + d] = 0.f; emb[24 + d] = 0.f;
        emb[32 + d] = cx;  emb[40 + d] = cy;
        emb[48 + d] = 1.f; emb[56 + d] = 1.f;
    }
    float acc = wg_b[h];
    const float* wr = wg_w + h * 64;
    #pragma unroll
    for (int d = 0; d < 64; d++) acc += emb[d] * wr[d];
    float w = fmaxf(acc, 0.f);
    g_tab[idx] = logf(fmaxf(w, 1e-6f));
}

__global__ void bias_fill() {
    int idx = blockIdx.x * blockDim.x + threadIdx.x;
    if (idx >= BIAS_HW) return;
    int i = idx / 1025, j = idx % 1025;
    if (i == 0 || j == 0) {
        #pragma unroll
        for (int h = 0; h < NH; h++) g_bias[(size_t)h * BIAS_HW + idx] = 0.f;
        return;
    }
    int p = i - 1, q = j - 1;
    int dr = abs((p >> 5) - (q >> 5));
    int dc = abs((p & 31) - (q & 31));
    int t = dr * 32 + dc;
    #pragma unroll
    for (int h = 0; h < NH; h++)
        g_bias[(size_t)h * BIAS_HW + idx] = g_tab[h * 1024 + t];
}

// ---------------- fused spatial attention (flash-style), 64q x 32k tiles ----------------
__global__ void __launch_bounds__(256) spatial_attn() {
    __shared__ __align__(16) float Qs[64][64];  // [d][q]
    __shared__ __align__(16) float Ks[64][32];  // [d][k]
    __shared__ __align__(16) float Vs[32][64];  // [k][d]
    __shared__ __align__(16) float Ps[32][64];  // [k][q]

    const int tid = threadIdx.x;
    const int ty = tid >> 4, tx = tid & 15;
    const int qtile = blockIdx.x;      // 0..16
    const int h = blockIdx.y;          // 0..11
    const int bt = blockIdx.z;         // 0..7
    const int q0 = qtile * 64;

    // load Q tile (transposed into [d][q])
    {
        int q = tid >> 2;
        int dbase = (tid & 3) * 16;
        int qc = min(q0 + q, 1024);
        const float* src = g_qkv + (size_t)(bt * 1025 + qc) * D3 + h * HD + dbase;
        #pragma unroll
        for (int z = 0; z < 16; z++) Qs[dbase + z][q] = src[z];
    }

    float mi[4] = {-1e30f, -1e30f, -1e30f, -1e30f};
    float li[4] = {0.f, 0.f, 0.f, 0.f};
    unsigned long long ap[4][2] = {};   // O accumulators: ap[i][j2] packs d-cols {2j2,2j2+1} of tx*4
    const float* brow_base = g_bias + (size_t)h * BIAS_HW;

    for (int kt = 0; kt < 33; kt++) {
        const int k0 = kt * 32;
        __syncthreads();   // protect Ks/Vs/Ps from previous iteration's readers
        {
            int k = tid >> 3;
            int dbase = (tid & 7) * 8;
            int kg = k0 + k;
            if (kg < 1025) {
                const float* src = g_qkv + (size_t)(bt * 1025 + kg) * D3 + 768 + h * HD + dbase;
                #pragma unroll
                for (int z = 0; z < 8; z++) {
                    Ks[dbase + z][k] = src[z];
                    Vs[k][dbase + z] = src[768 + z];
                }
            } else {
                #pragma unroll
                for (int z = 0; z < 8; z++) { Ks[dbase + z][k] = 0.f; Vs[k][dbase + z] = 0.f; }
            }
        }
        __syncthreads();

        // S = Q K^T  (thread: 4 queries x 2 keys) — packed over query pairs
        unsigned long long sp[2][2] = {};
        #pragma unroll 16
        for (int d = 0; d < 64; d++) {
            ulonglong2 qa = *(const ulonglong2*)&Qs[d][ty * 4];  // pairs (q0,q1),(q2,q3)
            float2 kb = *(const float2*)&Ks[d][tx * 2];
            unsigned long long kd0 = dup2(kb.x);
            unsigned long long kd1 = dup2(kb.y);
            FMA2(sp[0][0], qa.x, kd0); FMA2(sp[0][1], qa.x, kd1);
            FMA2(sp[1][0], qa.y, kd0); FMA2(sp[1][1], qa.y, kd1);
        }
        float sv[4][2];
        unpack2(sp[0][0], sv[0][0], sv[1][0]);
        unpack2(sp[0][1], sv[0][1], sv[1][1]);
        unpack2(sp[1][0], sv[2][0], sv[3][0]);
        unpack2(sp[1][1], sv[2][1], sv[3][1]);

        float pr[4][2];
        #pragma unroll
        for (int i = 0; i < 4; i++) {
            int qc = min(q0 + ty * 4 + i, 1024);
            const float* brow = brow_base + (size_t)qc * 1025;
            float lg[2];
            #pragma unroll
            for (int j = 0; j < 2; j++) {
                int kg = k0 + tx * 2 + j;
                float bz = brow[min(kg, 1024)];
                lg[j] = (kg < 1025) ? sv[i][j] * 0.125f + bz : -1e30f;
            }
            float rm = fmaxf(lg[0], lg[1]);
            #pragma unroll
            for (int o = 1; o < 16; o <<= 1) rm = fmaxf(rm, __shfl_xor_sync(0xffffffffu, rm, o));
            float mnew = fmaxf(mi[i], rm);
            float p0 = __expf(lg[0] - mnew), p1 = __expf(lg[1] - mnew);
            float rs = p0 + p1;
            #pragma unroll
            for (int o = 1; o < 16; o <<= 1) rs += __shfl_xor_sync(0xffffffffu, rs, o);
            float corr = __expf(mi[i] - mnew);
            li[i] = li[i] * corr + rs;
            mi[i] = mnew;
            unsigned long long cd = dup2(corr);
            MUL2(ap[i][0], ap[i][0], cd);
            MUL2(ap[i][1], ap[i][1], cd);
            pr[i][0] = p0; pr[i][1] = p1;
        }
        #pragma unroll
        for (int j = 0; j < 2; j++) {
            float4 pv = {pr[0][j], pr[1][j], pr[2][j], pr[3][j]};
            *(float4*)&Ps[tx * 2 + j][ty * 4] = pv;
        }
        __syncthreads();

        // O += P @ V — packed over V column pairs
        #pragma unroll 8
        for (int kk = 0; kk < 32; kk++) {
            float4 pv = *(const float4*)&Ps[kk][ty * 4];
            ulonglong2 vv = *(const ulonglong2*)&Vs[kk][tx * 4];
            unsigned long long pd;
            pd = dup2(pv.x); FMA2(ap[0][0], pd, vv.x); FMA2(ap[0][1], pd, vv.y);
            pd = dup2(pv.y); FMA2(ap[1][0], pd, vv.x); FMA2(ap[1][1], pd, vv.y);
            pd = dup2(pv.z); FMA2(ap[2][0], pd, vv.x); FMA2(ap[2][1], pd, vv.y);
            pd = dup2(pv.w); FMA2(ap[3][0], pd, vv.x); FMA2(ap[3][1], pd, vv.y);
        }
    }

    #pragma unroll
    for (int i = 0; i < 4; i++) {
        int qg = q0 + ty * 4 + i;
        if (qg < 1025) {
            float inv = 1.0f / li[i];
            float a0, a1, a2, a3;
            unpack2(ap[i][0], a0, a1);
            unpack2(ap[i][1], a2, a3);
            float4 o = {a0 * inv, a1 * inv, a2 * inv, a3 * inv};
            *(float4*)(g_att + (size_t)(bt * 1025 + qg) * DIMC + h * HD + tx * 4) = o;
        }
    }
}

// ---------------- elementwise: g_xt = x[:,1:,:] + tfc_out(g_att) ----------------
__global__ void add_xt(const float* __restrict__ x) {
    int i4 = blockIdx.x * blockDim.x + threadIdx.x;
    const int total = 8192 * 192;
    if (i4 >= total) return;
    int row = i4 / 192, c4 = i4 - row * 192;
    int bb = row >> 12, pos = row & 4095;
    float4 a = ((const float4*)g_att)[i4];
    float4 xv = ((const float4*)x)[(size_t)(bb * 4097 + 1 + pos) * 192 + c4];
    float4 r = {a.x + xv.x, a.y + xv.y, a.z + xv.z, a.w + xv.w};
    ((float4*)g_xt)[i4] = r;
}

// ---------------- assemble xout into d_out ----------------
__global__ void assemble(const float* __restrict__ x, float* __restrict__ out) {
    int i4 = blockIdx.x * blockDim.x + threadIdx.x;
    const int total = 2 * 4097 * 192;
    if (i4 >= total) return;
    int rem = i4 / 192, c4 = i4 - rem * 192;
    int bb = rem / 4097, n = rem - bb * 4097;
    const float4* res4 = (const float4*)g_res;
    float4 r;
    if (n == 0) {
        float4 a = ((const float4*)x)[i4];
        float4 s = {0.f, 0.f, 0.f, 0.f};
        #pragma unroll
        for (int t = 0; t < 4; t++) {
            float4 v = res4[(size_t)((bb * 4 + t) * 1025) * 192 + c4];
            s.x += v.x; s.y += v.y; s.z += v.z; s.w += v.w;
        }
        r = {a.x + 0.25f * s.x, a.y + 0.25f * s.y, a.z + 0.25f * s.z, a.w + 0.25f * s.w};
    } else {
        int st = n - 1, ss = st >> 2, t = st & 3;
        float4 a = ((const float4*)g_xt)[(size_t)(bb * 4096 + st) * 192 + c4];
        float4 v = res4[(size_t)((bb * 4 + t) * 1025 + 1 + ss) * 192 + c4];
        r = {a.x + v.x, a.y + v.y, a.z + v.z, a.w + v.w};
    }
    ((float4*)out)[i4] = r;
}

// ---------------- host launch sequence ----------------
extern "C" void kernel_launch(void* const* d_in, const int* in_sizes, int n_in,
                              void* d_out, int out_size) {
    const float* x        = (const float*)d_in[0];
    const float* norm1_g  = (const float*)d_in[1];
    const float* norm1_b  = (const float*)d_in[2];
    const float* qkv_w    = (const float*)d_in[3];
    const float* proj_w   = (const float*)d_in[4];
    const float* proj_b   = (const float*)d_in[5];
    const float* wg_w     = (const float*)d_in[6];
    const float* wg_b     = (const float*)d_in[7];
    const float* tnorm1_g = (const float*)d_in[8];
    const float* tnorm1_b = (const float*)d_in[9];
    const float* tqkv_w   = (const float*)d_in[10];
    const float* tproj_w  = (const float*)d_in[11];
    const float* tproj_b  = (const float*)d_in[12];
    const float* tfc_w    = (const float*)d_in[13];
    const float* tfc_b    = (const float*)d_in[14];
    const float* norm2_g  = (const float*)d_in[15];
    const float* norm2_b  = (const float*)d_in[16];
    const float* fc1_w    = (const float*)d_in[17];
    const float* fc1_b    = (const float*)d_in[18];
    const float* fc2_w    = (const float*)d_in[19];
    const float* fc2_b    = (const float*)d_in[20];
    float* out = (float*)d_out;

    float *ln, *qkv, *att, *res, *hbuf;
    cudaGetSymbolAddress((void**)&ln,   g_ln);
    cudaGetSymbolAddress((void**)&qkv,  g_qkv);
    cudaGetSymbolAddress((void**)&att,  g_att);
    cudaGetSymbolAddress((void**)&res,  g_res);
    cudaGetSymbolAddress((void**)&hbuf, g_h);

    // geometry bias: tiny factored table, then pure-store broadcast fill
    bias_table<<<(NH * 1024 + 255) / 256, 256>>>(wg_w, wg_b);
    bias_fill<<<(BIAS_HW + 255) / 256, 256>>>();

    // --- temporal branch ---
    ln_temporal<<<NTOK_T, 256>>>(x, tnorm1_g, tnorm1_b);
    sgemm_nt<E_NONE><<<dim3(D3 / 128, NTOK_T / 128), 256>>>(ln, tqkv_w, nullptr, qkv, NTOK_T, D3, DIMC);
    temporal_attn<<<3072, 256>>>();
    sgemm_nt<E_NONE><<<dim3(DIMC / 128, NTOK_T / 128), 256>>>(att, tproj_w, tproj_b, res, NTOK_T, DIMC, DIMC);
    sgemm_nt<E_NONE><<<dim3(DIMC / 128, NTOK_T / 128), 256>>>(res, tfc_w, tfc_b, att, NTOK_T, DIMC, DIMC);
    add_xt<<<(8192 * 192 + 255) / 256, 256>>>(x);

    // --- spatial branch ---
    ln_spatial<<<NTOK_S, 256>>>(x, norm1_g, norm1_b);
    sgemm_nt<E_NONE><<<dim3(D3 / 128, (NTOK_S + 127) / 128), 256>>>(ln, qkv_w, nullptr, qkv, NTOK_S, D3, DIMC);
    spatial_attn<<<dim3(17, NH, 8), 256>>>();
    sgemm_nt<E_NONE><<<dim3(DIMC / 128, (NTOK_S + 127) / 128), 256>>>(att, proj_w, proj_b, res, NTOK_S, DIMC, DIMC);
    assemble<<<(2 * 4097 * 192 + 255) / 256, 256>>>(x, out);

    // --- MLP ---
    ln_plain<<<NTOK_O, 256>>>(out, norm2_g, norm2_b);
    sgemm_nt<E_GELU><<<dim3(MLPH / 128, (NTOK_O + 127) / 128), 256>>>(ln, fc1_w, fc1_b, hbuf, NTOK_O, MLPH, DIMC);
    sgemm_nt<E_RES><<<dim3(DIMC / 128, (NTOK_O + 127) / 128), 256>>>(hbuf, fc2_w, fc2_b, out, NTOK_O, DIMC, MLPH);
}

// round 8
// speedup vs baseline: 1.1592x; 1.1435x over previous
#include <cuda_runtime.h>
#include <math.h>
#include <stdint.h>

// ---------------- problem constants ----------------
#define DIMC   768
#define D3     2304
#define NH     12
#define HD     64
#define MLPH   3072
#define NTOK_T 8192      // 2*4096 temporal tokens
#define NTOK_S 8200      // 8*1025 spatial tokens
#define NTOK_O 8194      // 2*4097 output tokens
#define PAD_ROWS 8320    // 65*128 (GEMM M padding)

// ---------------- scratch (device globals; no allocs allowed) ----------------
__device__ __align__(16) float g_ln  [PAD_ROWS * DIMC];
__device__ __align__(16) float g_qkv [PAD_ROWS * D3];
__device__ __align__(16) float g_att [PAD_ROWS * DIMC];
__device__ __align__(16) float g_res [PAD_ROWS * DIMC];
__device__ __align__(16) float g_xt  [8192 * DIMC];
__device__ __align__(16) float g_tab [NH * 32 * 32];
__device__ __align__(16) float g_h   [PAD_ROWS * MLPH];

// ---------------- packed f32x2 helpers (sm_100+ dual fp32 FMA per issue) ----------------
__device__ __forceinline__ unsigned long long dup2(float v) {
    unsigned long long r;
    unsigned u = __float_as_uint(v);
    asm("mov.b64 %0, {%1, %1};" : "=l"(r) : "r"(u));
    return r;
}
#define FMA2(acc, a, b) \
    asm("fma.rn.f32x2 %0, %1, %2, %3;" : "=l"(acc) : "l"(a), "l"(b), "l"(acc))
#define MUL2(dst, a, b) \
    asm("mul.rn.f32x2 %0, %1, %2;" : "=l"(dst) : "l"(a), "l"(b))
__device__ __forceinline__ void unpack2(unsigned long long p, float& lo, float& hi) {
    unsigned ulo, uhi;
    asm("mov.b64 {%0, %1}, %2;" : "=r"(ulo), "=r"(uhi) : "l"(p));
    lo = __uint_as_float(ulo); hi = __uint_as_float(uhi);
}

// ---------------- block reduction ----------------
__device__ __forceinline__ float block_reduce_sum(float v) {
    __shared__ float red[8];
    int lane = threadIdx.x & 31, wid = threadIdx.x >> 5;
    #pragma unroll
    for (int o = 16; o; o >>= 1) v += __shfl_xor_sync(0xffffffffu, v, o);
    if (lane == 0) red[wid] = v;
    __syncthreads();
    if (wid == 0) {
        float r = (lane < 8) ? red[lane] : 0.f;
        #pragma unroll
        for (int o = 4; o; o >>= 1) r += __shfl_xor_sync(0xffffffffu, r, o);
        if (lane == 0) red[0] = r;
    }
    __syncthreads();
    float s = red[0];
    __syncthreads();
    return s;
}

// LayerNorm of one 768-row; blockDim = 256
__device__ __forceinline__ void ln_row(const float* __restrict__ src,
                                       float* __restrict__ dst,
                                       const float* __restrict__ g,
                                       const float* __restrict__ b) {
    int t = threadIdx.x;
    float v0 = src[t], v1 = src[t + 256], v2 = src[t + 512];
    float s = block_reduce_sum(v0 + v1 + v2);
    float mean = s * (1.0f / 768.0f);
    float d0 = v0 - mean, d1 = v1 - mean, d2 = v2 - mean;
    float vs = block_reduce_sum(d0 * d0 + d1 * d1 + d2 * d2);
    float rstd = rsqrtf(vs * (1.0f / 768.0f) + 1e-5f);
    dst[t]       = d0 * rstd * g[t]       + b[t];
    dst[t + 256] = d1 * rstd * g[t + 256] + b[t + 256];
    dst[t + 512] = d2 * rstd * g[t + 512] + b[t + 512];
}

__global__ void ln_temporal(const float* __restrict__ x,
                            const float* __restrict__ g, const float* __restrict__ b) {
    int row = blockIdx.x;
    int bb = row >> 12, pos = row & 4095;
    ln_row(x + (size_t)(bb * 4097 + 1 + pos) * DIMC, g_ln + (size_t)row * DIMC, g, b);
}

__global__ void ln_spatial(const float* __restrict__ x,
                           const float* __restrict__ g, const float* __restrict__ b) {
    int row = blockIdx.x;
    int bt = row / 1025, n = row % 1025;
    int bb = bt >> 2, t = bt & 3;
    const float* src = (n == 0)
        ? x + (size_t)bb * 4097 * DIMC
        : g_xt + (size_t)(bb * 4096 + (n - 1) * 4 + t) * DIMC;
    ln_row(src, g_ln + (size_t)row * DIMC, g, b);
}

__global__ void ln_plain(const float* __restrict__ xo,
                         const float* __restrict__ g, const float* __restrict__ b) {
    int row = blockIdx.x;
    ln_row(xo + (size_t)row * DIMC, g_ln + (size_t)row * DIMC, g, b);
}

// ---------------- SGEMM: C[M,N] = A[M,K] @ W[N,K]^T (+bias) (+epilogue) ----------------
// BM=BN=128, BK=8, 256 threads, 8x8 microtile split 4+4 at stride 64
// (conflict-free LDS.128: column threads read CONSECUTIVE 16B chunks).
enum { E_NONE = 0, E_GELU = 1, E_RES = 2 };

template <int EPI>
__global__ void __launch_bounds__(256, 2)
sgemm_nt(const float* __restrict__ A, const float* __restrict__ W,
         const float* __restrict__ bias, float* __restrict__ C,
         int M, int N, int K) {
    __shared__ __align__(16) float As[8][128];
    __shared__ __align__(16) float Ws[8][128];
    const int tid = threadIdx.x;
    const int bm = blockIdx.y * 128;
    const int bn = blockIdx.x * 128;
    const int lrow = tid >> 1;
    const int lcol = (tid & 1) * 4;
    const int rg = tid >> 4;      // row group 0..15 -> rows {rg*4..+3, rg*4+64..+67}
    const int cg = tid & 15;      // col group 0..15 -> cols {cg*4..+3, cg*4+64..+67}

    unsigned long long acc[8][4] = {};   // [i:8 rows][j2: col pairs {cg*4+2*j2'} and +64]
    const float* Aptr = A + (size_t)(bm + lrow) * K + lcol;  // rows padded; safe
    const float* Wptr = W + (size_t)(bn + lrow) * K + lcol;

    for (int k0 = 0; k0 < K; k0 += 8) {
        float4 av = *(const float4*)(Aptr + k0);
        float4 wv = *(const float4*)(Wptr + k0);
        As[lcol + 0][lrow] = av.x; As[lcol + 1][lrow] = av.y;
        As[lcol + 2][lrow] = av.z; As[lcol + 3][lrow] = av.w;
        Ws[lcol + 0][lrow] = wv.x; Ws[lcol + 1][lrow] = wv.y;
        Ws[lcol + 2][lrow] = wv.z; Ws[lcol + 3][lrow] = wv.w;
        __syncthreads();
        #pragma unroll
        for (int kk = 0; kk < 8; kk++) {
            float4 a0 = *(const float4*)&As[kk][rg * 4];
            float4 a1 = *(const float4*)&As[kk][rg * 4 + 64];
            ulonglong2 w0 = *(const ulonglong2*)&Ws[kk][cg * 4];
            ulonglong2 w1 = *(const ulonglong2*)&Ws[kk][cg * 4 + 64];
            unsigned long long bp[4] = {w0.x, w0.y, w1.x, w1.y};
            float am[8] = {a0.x, a0.y, a0.z, a0.w, a1.x, a1.y, a1.z, a1.w};
            #pragma unroll
            for (int i = 0; i < 8; i++) {
                unsigned long long ad = dup2(am[i]);
                #pragma unroll
                for (int j = 0; j < 4; j++) FMA2(acc[i][j], ad, bp[j]);
            }
        }
        __syncthreads();
    }

    #pragma unroll
    for (int i = 0; i < 8; i++) {
        int row = bm + rg * 4 + (i & 3) + (i >> 2) * 64;
        if (row < M) {
            float* crow = C + (size_t)row * N + bn;
            #pragma unroll
            for (int j2 = 0; j2 < 4; j2++) {
                int cbase = cg * 4 + (j2 & 1) * 2 + (j2 >> 1) * 64;
                float v0, v1;
                unpack2(acc[i][j2], v0, v1);
                float vv[2] = {v0, v1};
                #pragma unroll
                for (int u = 0; u < 2; u++) {
                    int j = cbase + u;
                    float v = vv[u];
                    if (bias) v += bias[bn + j];
                    if (EPI == E_GELU) v = 0.5f * v * (1.0f + erff(v * 0.70710678118654752f));
                    else if (EPI == E_RES) v += crow[j];
                    crow[j] = v;
                }
            }
        }
    }
}

// ---------------- temporal attention: seq=4, one warp per (seq,head) ----------------
__global__ void temporal_attn() {
    int w = (blockIdx.x * blockDim.x + threadIdx.x) >> 5;
    int lane = threadIdx.x & 31;
    if (w >= 2048 * NH) return;
    int sq = w / NH, h = w % NH;
    int col = h * HD + lane;

    float q[4][2], k[4][2], v[4][2];
    #pragma unroll
    for (int t = 0; t < 4; t++) {
        const float* base = g_qkv + (size_t)(sq * 4 + t) * D3;
        q[t][0] = base[col];            q[t][1] = base[col + 32];
        k[t][0] = base[768 + col];      k[t][1] = base[768 + col + 32];
        v[t][0] = base[1536 + col];     v[t][1] = base[1536 + col + 32];
    }
    float sc[4][4];
    #pragma unroll
    for (int t = 0; t < 4; t++)
        #pragma unroll
        for (int u = 0; u < 4; u++) {
            float p = q[t][0] * k[u][0] + q[t][1] * k[u][1];
            #pragma unroll
            for (int o = 16; o; o >>= 1) p += __shfl_xor_sync(0xffffffffu, p, o);
            sc[t][u] = p * 0.125f;
        }
    #pragma unroll
    for (int t = 0; t < 4; t++) {
        float m = fmaxf(fmaxf(sc[t][0], sc[t][1]), fmaxf(sc[t][2], sc[t][3]));
        float e0 = __expf(sc[t][0] - m), e1 = __expf(sc[t][1] - m);
        float e2 = __expf(sc[t][2] - m), e3 = __expf(sc[t][3] - m);
        float inv = 1.0f / (e0 + e1 + e2 + e3);
        float o0 = (e0 * v[0][0] + e1 * v[1][0] + e2 * v[2][0] + e3 * v[3][0]) * inv;
        float o1 = (e0 * v[0][1] + e1 * v[1][1] + e2 * v[2][1] + e3 * v[3][1]) * inv;
        float* dst = g_att + (size_t)(sq * 4 + t) * DIMC + col;
        dst[0] = o0; dst[32] = o1;
    }
}

// ---------------- geometry bias factored table: 12 heads x 32 x 32 ----------------
// bias[h,i,j] (i,j>=1) depends ONLY on (|dpx|, |dpy|); cls row/col is 0.
__global__ void bias_table(const float* __restrict__ wg_w, const float* __restrict__ wg_b) {
    int idx = blockIdx.x * blockDim.x + threadIdx.x;
    if (idx >= NH * 1024) return;
    int h = idx >> 10;
    int rc = idx & 1023;
    int r = rc >> 5, c = rc & 31;     // |dpx|, |dpy| in 0..31
    const float invw = 1.0f / (1.0f + 1.0f / 32.0f);
    float dx = logf(fmaxf(((float)r / 32.0f) * invw, 0.001f));
    float dy = logf(fmaxf(((float)c / 32.0f) * invw, 0.001f));

    const float dm[8] = {1.0f, 0.42169650342f, 0.17782794100f, 0.074989420933f,
                         0.031622776602f, 0.013335214322f, 0.0056234132519f, 0.0023713737057f};
    float emb[64];
    float hdx = 100.0f * dx, hdy = 100.0f * dy;
    #pragma unroll
    for (int d = 0; d < 8; d++) {
        float sx, cx, sy, cy;
        sincosf(hdx * dm[d], &sx, &cx);
        sincosf(hdy * dm[d], &sy, &cy);
        emb[d] = sx;       emb[8 + d] = sy;
        emb[16 + d] = 0.f; emb[24 + d] = 0.f;
        emb[32 + d] = cx;  emb[40 + d] = cy;
        emb[48 + d] = 1.f; emb[56 + d] = 1.f;
    }
    float acc = wg_b[h];
    const float* wr = wg_w + h * 64;
    #pragma unroll
    for (int d = 0; d < 64; d++) acc += emb[d] * wr[d];
    float w = fmaxf(acc, 0.f);
    g_tab[idx] = logf(fmaxf(w, 1e-6f));
}

// ---------------- fused spatial attention (flash-style), 64q x 32k tiles ----------------
__global__ void __launch_bounds__(256) spatial_attn() {
    __shared__ __align__(16) float Qs[64][64];  // [d][q]
    __shared__ __align__(16) float Ks[64][32];  // [d][k]
    __shared__ __align__(16) float Vs[32][64];  // [k][d]
    __shared__ __align__(16) float Ps[32][68];  // [k][q] (+4 pad: kill 8-way store conflict)
    __shared__ float Tb[1024];                  // per-head bias table

    const int tid = threadIdx.x;
    const int ty = tid >> 4, tx = tid & 15;
    const int qtile = blockIdx.x;      // 0..16
    const int h = blockIdx.y;          // 0..11
    const int bt = blockIdx.z;         // 0..7
    const int q0 = qtile * 64;

    // load per-head bias table
    #pragma unroll
    for (int z = 0; z < 4; z++) Tb[tid + z * 256] = g_tab[h * 1024 + tid + z * 256];

    // load Q tile (transposed into [d][q])
    {
        int q = tid >> 2;
        int dbase = (tid & 3) * 16;
        int qc = min(q0 + q, 1024);
        const float* src = g_qkv + (size_t)(bt * 1025 + qc) * D3 + h * HD + dbase;
        #pragma unroll
        for (int z = 0; z < 16; z++) Qs[dbase + z][q] = src[z];
    }

    float mi[4] = {-1e30f, -1e30f, -1e30f, -1e30f};
    float li[4] = {0.f, 0.f, 0.f, 0.f};
    unsigned long long ap[4][2] = {};   // O accumulators (packed d-col pairs at tx*4)

    for (int kt = 0; kt < 33; kt++) {
        const int k0 = kt * 32;
        __syncthreads();   // protect Ks/Vs/Ps from previous iteration's readers (and Tb/Qs at kt=0)
        {
            int k = tid >> 3;
            int dbase = (tid & 7) * 8;
            int kg = k0 + k;
            if (kg < 1025) {
                const float* src = g_qkv + (size_t)(bt * 1025 + kg) * D3 + 768 + h * HD + dbase;
                #pragma unroll
                for (int z = 0; z < 8; z++) {
                    Ks[dbase + z][k] = src[z];
                    Vs[k][dbase + z] = src[768 + z];
                }
            } else {
                #pragma unroll
                for (int z = 0; z < 8; z++) { Ks[dbase + z][k] = 0.f; Vs[k][dbase + z] = 0.f; }
            }
        }
        __syncthreads();

        // S = Q K^T  (thread: 4 queries x 2 keys) — packed over query pairs
        unsigned long long sp[2][2] = {};
        #pragma unroll 16
        for (int d = 0; d < 64; d++) {
            ulonglong2 qa = *(const ulonglong2*)&Qs[d][ty * 4];  // pairs (q0,q1),(q2,q3)
            float2 kb = *(const float2*)&Ks[d][tx * 2];
            unsigned long long kd0 = dup2(kb.x);
            unsigned long long kd1 = dup2(kb.y);
            FMA2(sp[0][0], qa.x, kd0); FMA2(sp[0][1], qa.x, kd1);
            FMA2(sp[1][0], qa.y, kd0); FMA2(sp[1][1], qa.y, kd1);
        }
        float sv[4][2];
        unpack2(sp[0][0], sv[0][0], sv[1][0]);
        unpack2(sp[0][1], sv[0][1], sv[1][1]);
        unpack2(sp[1][0], sv[2][0], sv[3][0]);
        unpack2(sp[1][1], sv[2][1], sv[3][1]);

        float pr[4][2];
        #pragma unroll
        for (int i = 0; i < 4; i++) {
            int qc = min(q0 + ty * 4 + i, 1024);
            int prx = (qc - 1) >> 5, pry = (qc - 1) & 31;
            float lg[2];
            #pragma unroll
            for (int j = 0; j < 2; j++) {
                int kg = k0 + tx * 2 + j;
                float bz = 0.f;
                if (qc != 0 && kg != 0 && kg < 1025) {
                    int qq = kg - 1;
                    int dr = abs(prx - (qq >> 5));
                    int dc = abs(pry - (qq & 31));
                    bz = Tb[dr * 32 + dc];
                }
                lg[j] = (kg < 1025) ? sv[i][j] * 0.125f + bz : -1e30f;
            }
            float rm = fmaxf(lg[0], lg[1]);
            #pragma unroll
            for (int o = 1; o < 16; o <<= 1) rm = fmaxf(rm, __shfl_xor_sync(0xffffffffu, rm, o));
            float mnew = fmaxf(mi[i], rm);
            float p0 = __expf(lg[0] - mnew), p1 = __expf(lg[1] - mnew);
            float rs = p0 + p1;
            #pragma unroll
            for (int o = 1; o < 16; o <<= 1) rs += __shfl_xor_sync(0xffffffffu, rs, o);
            float corr = __expf(mi[i] - mnew);
            li[i] = li[i] * corr + rs;
            mi[i] = mnew;
            unsigned long long cd = dup2(corr);
            MUL2(ap[i][0], ap[i][0], cd);
            MUL2(ap[i][1], ap[i][1], cd);
            pr[i][0] = p0; pr[i][1] = p1;
        }
        #pragma unroll
        for (int j = 0; j < 2; j++) {
            float4 pv = {pr[0][j], pr[1][j], pr[2][j], pr[3][j]};
            *(float4*)&Ps[tx * 2 + j][ty * 4] = pv;
        }
        __syncthreads();

        // O += P @ V — packed over V column pairs
        #pragma unroll 8
        for (int kk = 0; kk < 32; kk++) {
            float4 pv = *(const float4*)&Ps[kk][ty * 4];
            ulonglong2 vv = *(const ulonglong2*)&Vs[kk][tx * 4];
            unsigned long long pd;
            pd = dup2(pv.x); FMA2(ap[0][0], pd, vv.x); FMA2(ap[0][1], pd, vv.y);
            pd = dup2(pv.y); FMA2(ap[1][0], pd, vv.x); FMA2(ap[1][1], pd, vv.y);
            pd = dup2(pv.z); FMA2(ap[2][0], pd, vv.x); FMA2(ap[2][1], pd, vv.y);
            pd = dup2(pv.w); FMA2(ap[3][0], pd, vv.x); FMA2(ap[3][1], pd, vv.y);
        }
    }

    #pragma unroll
    for (int i = 0; i < 4; i++) {
        int qg = q0 + ty * 4 + i;
        if (qg < 1025) {
            float inv = 1.0f / li[i];
            float a0, a1, a2, a3;
            unpack2(ap[i][0], a0, a1);
            unpack2(ap[i][1], a2, a3);
            float4 o = {a0 * inv, a1 * inv, a2 * inv, a3 * inv};
            *(float4*)(g_att + (size_t)(bt * 1025 + qg) * DIMC + h * HD + tx * 4) = o;
        }
    }
}

// ---------------- elementwise: g_xt = x[:,1:,:] + tfc_out(g_att) ----------------
__global__ void add_xt(const float* __restrict__ x) {
    int i4 = blockIdx.x * blockDim.x + threadIdx.x;
    const int total = 8192 * 192;
    if (i4 >= total) return;
    int row = i4 / 192, c4 = i4 - row * 192;
    int bb = row >> 12, pos = row & 4095;
    float4 a = ((const float4*)g_att)[i4];
    float4 xv = ((const float4*)x)[(size_t)(bb * 4097 + 1 + pos) * 192 + c4];
    float4 r = {a.x + xv.x, a.y + xv.y, a.z + xv.z, a.w + xv.w};
    ((float4*)g_xt)[i4] = r;
}

// ---------------- assemble xout into d_out ----------------
__global__ void assemble(const float* __restrict__ x, float* __restrict__ out) {
    int i4 = blockIdx.x * blockDim.x + threadIdx.x;
    const int total = 2 * 4097 * 192;
    if (i4 >= total) return;
    int rem = i4 / 192, c4 = i4 - rem * 192;
    int bb = rem / 4097, n = rem - bb * 4097;
    const float4* res4 = (const float4*)g_res;
    float4 r;
    if (n == 0) {
        float4 a = ((const float4*)x)[i4];
        float4 s = {0.f, 0.f, 0.f, 0.f};
        #pragma unroll
        for (int t = 0; t < 4; t++) {
            float4 v = res4[(size_t)((bb * 4 + t) * 1025) * 192 + c4];
            s.x += v.x; s.y += v.y; s.z += v.z; s.w += v.w;
        }
        r = {a.x + 0.25f * s.x, a.y + 0.25f * s.y, a.z + 0.25f * s.z, a.w + 0.25f * s.w};
    } else {
        int st = n - 1, ss = st >> 2, t = st & 3;
        float4 a = ((const float4*)g_xt)[(size_t)(bb * 4096 + st) * 192 + c4];
        float4 v = res4[(size_t)((bb * 4 + t) * 1025 + 1 + ss) * 192 + c4];
        r = {a.x + v.x, a.y + v.y, a.z + v.z, a.w + v.w};
    }
    ((float4*)out)[i4] = r;
}

// ---------------- host launch sequence ----------------
extern "C" void kernel_launch(void* const* d_in, const int* in_sizes, int n_in,
                              void* d_out, int out_size) {
    const float* x        = (const float*)d_in[0];
    const float* norm1_g  = (const float*)d_in[1];
    const float* norm1_b  = (const float*)d_in[2];
    const float* qkv_w    = (const float*)d_in[3];
    const float* proj_w   = (const float*)d_in[4];
    const float* proj_b   = (const float*)d_in[5];
    const float* wg_w     = (const float*)d_in[6];
    const float* wg_b     = (const float*)d_in[7];
    const float* tnorm1_g = (const float*)d_in[8];
    const float* tnorm1_b = (const float*)d_in[9];
    const float* tqkv_w   = (const float*)d_in[10];
    const float* tproj_w  = (const float*)d_in[11];
    const float* tproj_b  = (const float*)d_in[12];
    const float* tfc_w    = (const float*)d_in[13];
    const float* tfc_b    = (const float*)d_in[14];
    const float* norm2_g  = (const float*)d_in[15];
    const float* norm2_b  = (const float*)d_in[16];
    const float* fc1_w    = (const float*)d_in[17];
    const float* fc1_b    = (const float*)d_in[18];
    const float* fc2_w    = (const float*)d_in[19];
    const float* fc2_b    = (const float*)d_in[20];
    float* out = (float*)d_out;

    float *ln, *qkv, *att, *res, *hbuf;
    cudaGetSymbolAddress((void**)&ln,   g_ln);
    cudaGetSymbolAddress((void**)&qkv,  g_qkv);
    cudaGetSymbolAddress((void**)&att,  g_att);
    cudaGetSymbolAddress((void**)&res,  g_res);
    cudaGetSymbolAddress((void**)&hbuf, g_h);

    // geometry bias: tiny factored table only (looked up in-kernel)
    bias_table<<<(NH * 1024 + 255) / 256, 256>>>(wg_w, wg_b);

    // --- temporal branch ---
    ln_temporal<<<NTOK_T, 256>>>(x, tnorm1_g, tnorm1_b);
    sgemm_nt<E_NONE><<<dim3(D3 / 128, NTOK_T / 128), 256>>>(ln, tqkv_w, nullptr, qkv, NTOK_T, D3, DIMC);
    temporal_attn<<<3072, 256>>>();
    sgemm_nt<E_NONE><<<dim3(DIMC / 128, NTOK_T / 128), 256>>>(att, tproj_w, tproj_b, res, NTOK_T, DIMC, DIMC);
    sgemm_nt<E_NONE><<<dim3(DIMC / 128, NTOK_T / 128), 256>>>(res, tfc_w, tfc_b, att, NTOK_T, DIMC, DIMC);
    add_xt<<<(8192 * 192 + 255) / 256, 256>>>(x);

    // --- spatial branch ---
    ln_spatial<<<NTOK_S, 256>>>(x, norm1_g, norm1_b);
    sgemm_nt<E_NONE><<<dim3(D3 / 128, (NTOK_S + 127) / 128), 256>>>(ln, qkv_w, nullptr, qkv, NTOK_S, D3, DIMC);
    spatial_attn<<<dim3(17, NH, 8), 256>>>();
    sgemm_nt<E_NONE><<<dim3(DIMC / 128, (NTOK_S + 127) / 128), 256>>>(att, proj_w, proj_b, res, NTOK_S, DIMC, DIMC);
    assemble<<<(2 * 4097 * 192 + 255) / 256, 256>>>(x, out);

    // --- MLP ---
    ln_plain<<<NTOK_O, 256>>>(out, norm2_g, norm2_b);
    sgemm_nt<E_GELU><<<dim3(MLPH / 128, (NTOK_O + 127) / 128), 256>>>(ln, fc1_w, fc1_b, hbuf, NTOK_O, MLPH, DIMC);
    sgemm_nt<E_RES><<<dim3(DIMC / 128, (NTOK_O + 127) / 128), 256>>>(hbuf, fc2_w, fc2_b, out, NTOK_O, DIMC, MLPH);
}